// round 9
// baseline (speedup 1.0000x reference)
#include <cuda_runtime.h>

// Biquad DF2T, B=512, T=48000, fp32 — SINGLE-PASS chained scan with
// decoupled lookback (exact, no truncation).
//
//   prep:  per channel compute M = A^C (fp64 repeated squaring) + zero flags.
//   fused: per (chunk, channel-group) warp:
//     phase 1: local recurrence from z=0 over C_LEN samples -> aggregate w
//              (publish w, flag=1)
//     lookback: compose predecessors' aggregates (P += Mp*w_j; Mp *= M),
//              batched with ballot'd flag checks, early-exit on any published
//              inclusive prefix -> z_start (publish inclusive, flag=2)
//     phase 2: recurrence from z_start, write y (x re-read hits L2).
//
// DRAM traffic ~190 MB (x once + y once) vs 282 MB for the 3-kernel version.
// Progress-safe: lookback waits only on strictly lower blockIdx (scheduled
// earlier under CLC bid-order placement), and __launch_bounds__(128,8) keeps
// all 1000 blocks co-resident (135KB smem/SM < 228KB).

#define B_CH    512
#define T_LEN   48000
#define C_LEN   192
#define K_CHK   250          // T_LEN / C_LEN
#define NGR     6            // 32-sample groups per chunk
#define WPB     4
#define NGRP    16           // channel groups of 32
#define NBLK    ((NGRP * K_CHK) / WPB)   // 1000
#define LB_BATCH 16

__device__ float4 g_M[B_CH];              // A^C per channel
__device__ float2 g_wz [K_CHK * B_CH];    // aggregates
__device__ float2 g_inc[K_CHK * B_CH];    // inclusive prefixes
__device__ int    g_flag[K_CHK * NGRP];   // 0=none 1=aggregate 2=inclusive

__device__ __forceinline__ int ld_flag(const int* p) {
    int v;
    asm volatile("ld.global.cg.b32 %0, [%1];" : "=r"(v) : "l"(p) : "memory");
    return v;
}
__device__ __forceinline__ void st_flag(int* p, int v) {
    asm volatile("st.global.cg.b32 [%0], %1;" :: "l"(p), "r"(v) : "memory");
}

__global__ void biquad_prep(const float* __restrict__ a1p,
                            const float* __restrict__ a2p)
{
    const int t = blockIdx.x * blockDim.x + threadIdx.x;
    if (t < K_CHK * NGRP) g_flag[t] = 0;
    if (t < B_CH) {
        const double a1 = (double)a1p[t];
        const double a2 = (double)a2p[t];
        double r00 = 1.0, r01 = 0.0, r10 = 0.0, r11 = 1.0;
        double p00 = -a1, p01 = 1.0, p10 = -a2, p11 = 0.0;
        int e = C_LEN;
        while (e) {
            if (e & 1) {
                double n00 = r00*p00 + r01*p10, n01 = r00*p01 + r01*p11;
                double n10 = r10*p00 + r11*p10, n11 = r10*p01 + r11*p11;
                r00 = n00; r01 = n01; r10 = n10; r11 = n11;
            }
            e >>= 1;
            if (e) {
                double q00 = p00*p00 + p01*p10, q01 = p00*p01 + p01*p11;
                double q10 = p10*p00 + p11*p10, q11 = p10*p01 + p11*p11;
                p00 = q00; p01 = q01; p10 = q10; p11 = q11;
            }
        }
        g_M[t] = make_float4((float)r00, (float)r01, (float)r10, (float)r11);
    }
}

__global__ __launch_bounds__(WPB * 32, 8) void biquad_fused(
    const float* __restrict__ x,
    const float* __restrict__ b0p, const float* __restrict__ b1p,
    const float* __restrict__ b2p, const float* __restrict__ a1p,
    const float* __restrict__ a2p, float* __restrict__ out)
{
    __shared__ float tile[WPB][32][33];   // pad-33: conflict-free everywhere

    const int w    = threadIdx.x >> 5;
    const int lane = threadIdx.x & 31;
    const int wg   = blockIdx.x * WPB + w;
    const int cg   = wg & (NGRP - 1);
    const int k    = wg >> 4;
    const int ch   = cg * 32 + lane;

    const float b0  = b0p[ch], b1 = b1p[ch], b2 = b2p[ch];
    const float na1 = -a1p[ch], na2 = -a2p[ch];

    const int lr = lane >> 3;          // 0..3
    const int lc = (lane & 7) * 4;     // 0..28
    const float* __restrict__ xbase = x + (size_t)(cg * 32) * T_LEN + k * C_LEN;
    float* __restrict__ obase = out + (size_t)(cg * 32) * T_LEN + k * C_LEN;

    float4 r[8];

    // ── Phase 1: local recurrence from z=0 -> aggregate w ──────────────
    float z1 = 0.0f, z2 = 0.0f;
    #pragma unroll
    for (int i = 0; i < 8; i++)
        r[i] = *reinterpret_cast<const float4*>(
            xbase + (size_t)(i * 4 + lr) * T_LEN + lc);

    #pragma unroll 1
    for (int g = 0; g < NGR; g++) {
        #pragma unroll
        for (int i = 0; i < 8; i++) {
            const int rr = i * 4 + lr;
            tile[w][rr][lc + 0] = r[i].x;
            tile[w][rr][lc + 1] = r[i].y;
            tile[w][rr][lc + 2] = r[i].z;
            tile[w][rr][lc + 3] = r[i].w;
        }
        __syncwarp();
        if (g + 1 < NGR) {
            #pragma unroll
            for (int i = 0; i < 8; i++)
                r[i] = *reinterpret_cast<const float4*>(
                    xbase + (size_t)(i * 4 + lr) * T_LEN + (g + 1) * 32 + lc);
        }
        #pragma unroll
        for (int j = 0; j < 32; j++) {
            const float xv = tile[w][lane][j];
            const float y  = fmaf(b0, xv, z1);
            const float t  = fmaf(b1, xv, z2);
            z1 = fmaf(na1, y, t);
            z2 = fmaf(na2, y, b2 * xv);
        }
        __syncwarp();
    }
    const float wa1 = z1, wa2 = z2;

    // Publish aggregate.
    __stcg(&g_wz[k * B_CH + ch], make_float2(wa1, wa2));
    __syncwarp();
    __threadfence();

    const float4 Mv = g_M[ch];
    const float m00 = Mv.x, m01 = Mv.y, m10 = Mv.z, m11 = Mv.w;

    // ── Lookback -> z_start ────────────────────────────────────────────
    float zs1, zs2;
    if (k == 0) {
        zs1 = 0.0f; zs2 = 0.0f;
        __stcg(&g_inc[ch], make_float2(wa1, wa2));   // M*0 + w
        __syncwarp();
        __threadfence();
        if (lane == 0) st_flag(&g_flag[cg], 2);
    } else {
        if (lane == 0) st_flag(&g_flag[k * NGRP + cg], 1);

        float P1 = 0.0f, P2 = 0.0f;
        float p00 = 1.0f, p01 = 0.0f, p10 = 0.0f, p11 = 1.0f;
        int j = k - 1;
        bool done = false;
        while (!done) {
            int f = 0;
            if (lane <= j) f = ld_flag(&g_flag[(j - lane) * NGRP + cg]);
            const unsigned ready = __ballot_sync(0xffffffffu, f >= 1);
            const unsigned incm  = __ballot_sync(0xffffffffu, f == 2);
            int run = (~ready == 0u) ? 32 : (__ffs(~ready) - 1);
            const int avail = j + 1;
            if (run > avail) run = avail;
            if (run == 0) { __nanosleep(128); continue; }

            int take = run > LB_BATCH ? LB_BATCH : run;
            const int incpos = __ffs(incm) - 1;
            const bool useInc = (incpos >= 0 && incpos < take);
            if (useInc) take = incpos + 1;

            __threadfence();
            float2 buf[LB_BATCH];
            #pragma unroll
            for (int i = 0; i < LB_BATCH; i++) {
                if (i < take) {
                    const float2* src = (useInc && i == take - 1)
                        ? &g_inc[(j - i) * B_CH + ch]
                        : &g_wz [(j - i) * B_CH + ch];
                    buf[i] = __ldcg(src);
                }
            }
            #pragma unroll
            for (int i = 0; i < LB_BATCH; i++) {
                if (i < take) {
                    const float2 v = buf[i];
                    if (useInc && i == take - 1) {
                        zs1 = fmaf(p00, v.x, fmaf(p01, v.y, P1));
                        zs2 = fmaf(p10, v.x, fmaf(p11, v.y, P2));
                        done = true;
                    } else {
                        P1 = fmaf(p00, v.x, fmaf(p01, v.y, P1));
                        P2 = fmaf(p10, v.x, fmaf(p11, v.y, P2));
                        const float q00 = fmaf(p00, m00, p01 * m10);
                        const float q01 = fmaf(p00, m01, p01 * m11);
                        const float q10 = fmaf(p10, m00, p11 * m10);
                        const float q11 = fmaf(p10, m01, p11 * m11);
                        p00 = q00; p01 = q01; p10 = q10; p11 = q11;
                    }
                }
            }
            if (!done) {
                j -= take;
                if (j < 0) { zs1 = P1; zs2 = P2; done = true; }  // chunk 0 base
            }
        }

        if (k < K_CHK - 1) {
            const float i1 = fmaf(m00, zs1, fmaf(m01, zs2, wa1));
            const float i2 = fmaf(m10, zs1, fmaf(m11, zs2, wa2));
            __stcg(&g_inc[k * B_CH + ch], make_float2(i1, i2));
            __syncwarp();
            __threadfence();
            if (lane == 0) st_flag(&g_flag[k * NGRP + cg], 2);
        }
    }

    // ── Phase 2: recurrence from z_start, write y ──────────────────────
    z1 = zs1; z2 = zs2;
    #pragma unroll
    for (int i = 0; i < 8; i++)
        r[i] = __ldcs(reinterpret_cast<const float4*>(
            xbase + (size_t)(i * 4 + lr) * T_LEN + lc));

    #pragma unroll 1
    for (int g = 0; g < NGR; g++) {
        #pragma unroll
        for (int i = 0; i < 8; i++) {
            const int rr = i * 4 + lr;
            tile[w][rr][lc + 0] = r[i].x;
            tile[w][rr][lc + 1] = r[i].y;
            tile[w][rr][lc + 2] = r[i].z;
            tile[w][rr][lc + 3] = r[i].w;
        }
        __syncwarp();
        if (g + 1 < NGR) {
            #pragma unroll
            for (int i = 0; i < 8; i++)
                r[i] = __ldcs(reinterpret_cast<const float4*>(
                    xbase + (size_t)(i * 4 + lr) * T_LEN + (g + 1) * 32 + lc));
        }
        #pragma unroll
        for (int j = 0; j < 32; j++) {
            const float xv = tile[w][lane][j];
            const float y  = fmaf(b0, xv, z1);
            const float t  = fmaf(b1, xv, z2);
            z1 = fmaf(na1, y, t);
            z2 = fmaf(na2, y, b2 * xv);
            tile[w][lane][j] = y;     // own row: no hazard
        }
        __syncwarp();
        #pragma unroll
        for (int i = 0; i < 8; i++) {
            const int rr = i * 4 + lr;
            const float* src = &tile[w][rr][lc];
            float4 vv;
            vv.x = src[0]; vv.y = src[1]; vv.z = src[2]; vv.w = src[3];
            __stcs(reinterpret_cast<float4*>(
                obase + (size_t)rr * T_LEN + g * 32 + lc), vv);
        }
        __syncwarp();
    }
}

extern "C" void kernel_launch(void* const* d_in, const int* in_sizes, int n_in,
                              void* d_out, int out_size)
{
    const float* x  = (const float*)d_in[0];
    const float* b0 = (const float*)d_in[1];
    const float* b1 = (const float*)d_in[2];
    const float* b2 = (const float*)d_in[3];
    const float* a1 = (const float*)d_in[4];
    const float* a2 = (const float*)d_in[5];
    float* out = (float*)d_out;

    biquad_prep<<<16, 256>>>(a1, a2);
    biquad_fused<<<NBLK, WPB * 32>>>(x, b0, b1, b2, a1, a2, out);
}

// round 10
// speedup vs baseline: 1.2284x; 1.2284x over previous
#include <cuda_runtime.h>

// Biquad DF2T, B=512, T=48000, fp32 — chunked scan with superposition split.
//   Pass 1: read x (.cs), run recurrence from z=0, WRITE y_zero to out
//           (default policy -> dirty in L2) + aggregate w per chunk.
//   Combine: z_start[k+1] = A^C z_start[k] + w[k] (A^C fp64), pipelined.
//   Pass 3: y_true[n] = y_zero[n] + (T^n z_start)_1 — no x read, no b coeffs.
//           Reads y_zero (L2 hits), adds register-computed correction,
//           overwrites same lines => y_zero never reaches DRAM.
// Ideal DRAM traffic: 94 MB (x) + 94 MB (final y) = 188 MB.

#define B_CH   512
#define T_LEN  48000
#define C_LEN  160
#define K_CHK  300          // T_LEN / C_LEN
#define NGR    5            // 32-sample groups per chunk
#define WPB    4
#define NGRP   16           // channel groups of 32
#define NBLK   ((NGRP * K_CHK) / WPB)   // 1200

__device__ float2 g_wz[K_CHK * B_CH];   // zero-state chunk-end states
__device__ float2 g_zs[K_CHK * B_CH];   // true chunk-start states

// ── Pass 1: y_zero + aggregates ──────────────────────────────────────────
__global__ __launch_bounds__(WPB * 32) void biquad_pass1(
    const float* __restrict__ x,
    const float* __restrict__ b0p, const float* __restrict__ b1p,
    const float* __restrict__ b2p, const float* __restrict__ a1p,
    const float* __restrict__ a2p, float* __restrict__ out)
{
    __shared__ float tile[WPB][32][33];

    const int w    = threadIdx.x >> 5;
    const int lane = threadIdx.x & 31;
    const int wg   = blockIdx.x * WPB + w;
    const int cg   = wg & (NGRP - 1);
    const int k    = wg >> 4;
    const int ch   = cg * 32 + lane;

    const float b0  = b0p[ch], b1 = b1p[ch], b2 = b2p[ch];
    const float na1 = -a1p[ch], na2 = -a2p[ch];

    const int lr = lane >> 3;
    const int lc = (lane & 7) * 4;
    const float* __restrict__ xbase = x + (size_t)(cg * 32) * T_LEN + k * C_LEN;
    float* __restrict__ obase = out + (size_t)(cg * 32) * T_LEN + k * C_LEN;

    float z1 = 0.0f, z2 = 0.0f;
    float4 r[8];
    #pragma unroll
    for (int i = 0; i < 8; i++)
        r[i] = __ldcs(reinterpret_cast<const float4*>(
            xbase + (size_t)(i * 4 + lr) * T_LEN + lc));

    #pragma unroll 1
    for (int g = 0; g < NGR; g++) {
        #pragma unroll
        for (int i = 0; i < 8; i++) {
            const int rr = i * 4 + lr;
            tile[w][rr][lc + 0] = r[i].x;
            tile[w][rr][lc + 1] = r[i].y;
            tile[w][rr][lc + 2] = r[i].z;
            tile[w][rr][lc + 3] = r[i].w;
        }
        __syncwarp();
        if (g + 1 < NGR) {
            #pragma unroll
            for (int i = 0; i < 8; i++)
                r[i] = __ldcs(reinterpret_cast<const float4*>(
                    xbase + (size_t)(i * 4 + lr) * T_LEN + (g + 1) * 32 + lc));
        }
        #pragma unroll
        for (int j = 0; j < 32; j++) {
            const float xv = tile[w][lane][j];
            const float y  = fmaf(b0, xv, z1);
            const float t  = fmaf(b1, xv, z2);
            z1 = fmaf(na1, y, t);
            z2 = fmaf(na2, y, b2 * xv);
            tile[w][lane][j] = y;        // y_zero, own row
        }
        __syncwarp();
        // Default-policy store: keep y_zero resident (dirty) in L2.
        #pragma unroll
        for (int i = 0; i < 8; i++) {
            const int rr = i * 4 + lr;
            const float* src = &tile[w][rr][lc];
            float4 vv;
            vv.x = src[0]; vv.y = src[1]; vv.z = src[2]; vv.w = src[3];
            *reinterpret_cast<float4*>(
                obase + (size_t)rr * T_LEN + g * 32 + lc) = vv;
        }
        __syncwarp();
    }

    g_wz[k * B_CH + ch] = make_float2(z1, z2);
}

// ── Combine (software-pipelined, from R7) ────────────────────────────────
#define CB      15
#define NBATCH  (K_CHK / CB)       // 20 (even)

__global__ void biquad_combine(const float* __restrict__ a1p,
                               const float* __restrict__ a2p)
{
    const int b = blockIdx.x * blockDim.x + threadIdx.x;
    if (b >= B_CH) return;

    const double a1 = (double)a1p[b];
    const double a2 = (double)a2p[b];

    double r00 = 1.0, r01 = 0.0, r10 = 0.0, r11 = 1.0;
    double p00 = -a1, p01 = 1.0, p10 = -a2, p11 = 0.0;
    int e = C_LEN;
    while (e) {
        if (e & 1) {
            double n00 = r00*p00 + r01*p10, n01 = r00*p01 + r01*p11;
            double n10 = r10*p00 + r11*p10, n11 = r10*p01 + r11*p11;
            r00 = n00; r01 = n01; r10 = n10; r11 = n11;
        }
        e >>= 1;
        if (e) {
            double q00 = p00*p00 + p01*p10, q01 = p00*p01 + p01*p11;
            double q10 = p10*p00 + p11*p10, q11 = p10*p01 + p11*p11;
            p00 = q00; p01 = q01; p10 = q10; p11 = q11;
        }
    }
    const float m00 = (float)r00, m01 = (float)r01;
    const float m10 = (float)r10, m11 = (float)r11;

    float z1 = 0.0f, z2 = 0.0f;
    float2 wA[CB], wB[CB];

    auto loadb = [&](float2* buf, int t) {
        #pragma unroll
        for (int i = 0; i < CB; i++)
            buf[i] = g_wz[(t * CB + i) * B_CH + b];
    };
    auto procb = [&](const float2* buf, int t) {
        #pragma unroll
        for (int i = 0; i < CB; i++) {
            g_zs[(t * CB + i) * B_CH + b] = make_float2(z1, z2);
            const float n1 = fmaf(m00, z1, fmaf(m01, z2, buf[i].x));
            const float n2 = fmaf(m10, z1, fmaf(m11, z2, buf[i].y));
            z1 = n1; z2 = n2;
        }
    };

    loadb(wA, 0);
    #pragma unroll 1
    for (int t = 0; t < NBATCH; t += 2) {
        loadb(wB, t + 1);
        procb(wA, t);
        if (t + 2 < NBATCH) loadb(wA, t + 2);
        procb(wB, t + 1);
    }
}

// ── Pass 3: add homogeneous correction (no x, no b) ─────────────────────
__global__ __launch_bounds__(WPB * 32) void biquad_correct(
    const float* __restrict__ a1p, const float* __restrict__ a2p,
    float* __restrict__ out)
{
    __shared__ float tile[WPB][32][33];

    const int w    = threadIdx.x >> 5;
    const int lane = threadIdx.x & 31;
    const int wg   = blockIdx.x * WPB + w;
    const int cg   = wg & (NGRP - 1);
    const int k    = wg >> 4;
    const int ch   = cg * 32 + lane;

    const float na1 = -a1p[ch], na2 = -a2p[ch];
    const float2 zz = g_zs[k * B_CH + ch];
    float c1 = zz.x, c2 = zz.y;

    const int lr = lane >> 3;
    const int lc = (lane & 7) * 4;
    float* __restrict__ obase = out + (size_t)(cg * 32) * T_LEN + k * C_LEN;

    #pragma unroll 1
    for (int g = 0; g < NGR; g++) {
        // Issue y_zero loads first; the 2-FMA/sample correction chain below
        // (~130 cyc) hides their (mostly-L2) latency.
        float4 r[8];
        #pragma unroll
        for (int i = 0; i < 8; i++)
            r[i] = *reinterpret_cast<const float4*>(
                obase + (size_t)(i * 4 + lr) * T_LEN + g * 32 + lc);

        // Correction series for this lane's channel: store c1, step c = T c.
        #pragma unroll
        for (int j = 0; j < 32; j++) {
            tile[w][lane][j] = c1;
            const float n1 = fmaf(na1, c1, c2);
            c2 = na2 * c1;
            c1 = n1;
        }
        __syncwarp();

        // Gather transposed corrections, add to y_zero, store final y.
        #pragma unroll
        for (int i = 0; i < 8; i++) {
            const int rr = i * 4 + lr;
            const float* src = &tile[w][rr][lc];
            float4 vv = r[i];
            vv.x += src[0]; vv.y += src[1]; vv.z += src[2]; vv.w += src[3];
            *reinterpret_cast<float4*>(
                obase + (size_t)rr * T_LEN + g * 32 + lc) = vv;
        }
        __syncwarp();
    }
}

extern "C" void kernel_launch(void* const* d_in, const int* in_sizes, int n_in,
                              void* d_out, int out_size)
{
    const float* x  = (const float*)d_in[0];
    const float* b0 = (const float*)d_in[1];
    const float* b1 = (const float*)d_in[2];
    const float* b2 = (const float*)d_in[3];
    const float* a1 = (const float*)d_in[4];
    const float* a2 = (const float*)d_in[5];
    float* out = (float*)d_out;

    biquad_pass1<<<NBLK, WPB * 32>>>(x, b0, b1, b2, a1, a2, out);
    biquad_combine<<<16, 32>>>(a1, a2);
    biquad_correct<<<NBLK, WPB * 32>>>(a1, a2, out);
}